// round 17
// baseline (speedup 1.0000x reference)
#include <cuda_runtime.h>
#include <math.h>

// CTC batch cost (keras.backend.ctc_batch_cost, full lengths, blank=C-1).
// Forward/backward split: warp pair per batch row; fwd computes alpha_255
// (t=1..255), bwd computes beta_255 (t=511..256); loss = -log(sum alpha*beta).
// Linear space, per-lane power-of-2 renorm every 8 steps (exact scaling).
// KPL=4 parity mapping: s = 4*lane + k; slots 0,2 blank (broadcast LDS),
// slots 1,3 labels; state 128 = scalar 'atop' valid in lane 31 only.
// q-values register-double-buffered at half-chunk (8-step) granularity so
// LDS gather latency is hidden a full compute block ahead.
//
// y_true [B=512, L=64] int32, y_pred [B=512, T=512, C=96] f32, out [B,1] f32.

constexpr int T_DIM = 512;
constexpr int C_DIM = 96;
constexpr int L_DIM = 64;
constexpr int BLANK = C_DIM - 1;       // 95
constexpr int CH    = 16;              // t-rows per chunk
constexpr int STG   = 4;               // smem ring stages per warp
constexpr int NCH   = 16;              // chunks per direction (256/16)
constexpr int NCHG  = 32;              // global chunks (512/16)
constexpr int ROWS_PB = 4;             // batch rows per block (8 warps)
constexpr float EPSF = 1e-7f;

constexpr int CHF    = CH * C_DIM;                       // 1536 floats/chunk
constexpr int RING_F = 8 * STG * CHF;                    // 49152 floats
constexpr int SMEM_BYTES = RING_F * 4 + ROWS_PB*32*5*4 + ROWS_PB*32*4;

#define FULLMASK 0xffffffffu

__global__ void __launch_bounds__(256, 1)
ctc_fb_kernel(const int* __restrict__ y_true,
              const float* __restrict__ y_pred,
              float* __restrict__ out, int B)
{
    extern __shared__ float smem[];
    float* ring = smem;                                   // [8][STG][1536]
    float* resB = ring + RING_F;                          // [4][32][5]
    int*   resE = (int*)(resB + ROWS_PB * 32 * 5);        // [4][32]

    const int tid  = threadIdx.x;
    const int warp = tid >> 5, lane = tid & 31;
    const int rowi = warp >> 1, dir = warp & 1;           // 0=fwd, 1=bwd
    const int b = blockIdx.x * ROWS_PB + rowi;

    const float* __restrict__ P = y_pred + (size_t)b * (size_t)(T_DIM * C_DIM);
    const int* __restrict__ lab = y_true + (size_t)b * L_DIM;

    // Labels for this lane's two odd states (s=4L+1 -> lab[2L], s=4L+3 -> lab[2L+1]).
    int l1 = lab[2 * lane], l3 = lab[2 * lane + 1];
    int col1 = max(0, min(C_DIM - 1, l1));
    int col3 = max(0, min(C_DIM - 1, l3));
    // skip(s) for odd s>=3: lab[j] != lab[j-1], j=(s-1)/2.
    float skF1 = (lane >= 1 && l1 != lab[2 * lane - 1]) ? 1.f : 0.f; // skip(4L+1)
    float skF3 = (l3 != l1) ? 1.f : 0.f;                             // skip(4L+3)
    float skB3 = (lane < 31 && lab[2 * lane + 2] != l3) ? 1.f : 0.f; // skip(4L+5)
    const float sk1 = dir ? skF3 : skF1;     // bwd slot1 uses skip(4L+3)
    const float sk3 = dir ? skB3 : skF3;
    const float t31f = (lane == 31) ? 1.f : 0.f;

    // state slots (alpha fwd / beta bwd); true value = a[k] * 2^E.
    // atop = state 128, meaningful in lane 31 only (its own scale).
    float a[4];
#pragma unroll
    for (int k = 0; k < 4; ++k) a[k] = 0.f;
    float atop = 0.f;
    if (dir == 0) {
        if (lane == 0) { a[0] = P[BLANK] + EPSF; a[1] = P[col1] + EPSF; }
    } else {
        if (lane == 31) a[3] = 1.f;    // state 127
        atop = 1.f;                    // state 128
    }
    int E = 0;
    const bool bnd = (dir == 0) ? (lane == 0) : (lane == 31);
    float f = bnd ? 0.f : 1.f;

    float* wring = ring + warp * STG * CHF;

    // producer: coalesced cp.async of one 16-row chunk (6144 B)
    auto issue = [&](int i) {                 // i = 0..15 (warp-local order)
        int c = dir ? (NCHG - 1 - i) : i;     // global chunk id
        const float4* g = (const float4*)(P + (size_t)c * CHF);
        unsigned sa = (unsigned)__cvta_generic_to_shared(
            wring + (i & (STG - 1)) * CHF);
#pragma unroll
        for (int j = 0; j < 12; ++j) {        // 384 float4 / 32 lanes
            int idx = lane + 32 * j;
            asm volatile("cp.async.cg.shared.global [%0], [%1], 16;\n"
                         :: "r"(sa + idx * 16), "l"(g + idx));
        }
        asm volatile("cp.async.commit_group;\n" ::: "memory");
    };

    // batch-load one half-chunk (8 steps x 3 probs) into registers.
    // base/stp give the step->row map (fwd ascending, bwd descending).
    auto load_half = [&](float (&q)[24], const float* sb, int base, int stp) {
        const float* pB = sb + BLANK;
        const float* p1 = sb + col1;
        const float* p3 = sb + col3;
#pragma unroll
        for (int j = 0; j < 8; ++j) {
            int r = (base + stp * j) * C_DIM;
            q[3*j+0] = pB[r];
            q[3*j+1] = p1[r];
            q[3*j+2] = p3[r];
        }
    };

    auto step_fwd = [&](float qb, float q1, float q3) {
        float am1 = __shfl_up_sync(FULLMASK, a[3], 1) * f;  // alpha(4L-1)
        float n0 = (a[0] + am1) * qb;
        float n1 = fmaf(sk1, am1, a[1] + a[0]) * q1;
        float n2 = (a[2] + a[1]) * qb;
        float n3 = fmaf(sk3, a[1], a[3] + a[2]) * q3;
        atop = (atop + a[3]) * qb;          // lane 31: a[3] == alpha(127)
        a[0]=n0; a[1]=n1; a[2]=n2; a[3]=n3;
    };

    auto step_bwd = [&](float qb, float q1, float q3) {
        float g0 = qb*a[0], g1 = q1*a[1], g2 = qb*a[2], g3 = q3*a[3];
        float gt = qb * atop;                               // g(128), lane31
        float gn0 = __shfl_down_sync(FULLMASK, g0, 1) * f;  // g(4L+4)
        float gn1 = __shfl_down_sync(FULLMASK, g1, 1) * f;  // g(4L+5)
        float n0 = g0 + g1;
        float n1 = fmaf(sk1, g3, g1 + g2);
        float n2 = g2 + g3;
        float n3 = fmaf(t31f, gt, fmaf(sk3, gn1, g3 + gn0));
        atop = gt;                                          // beta(128)
        a[0]=n0; a[1]=n1; a[2]=n2; a[3]=n3;
    };

    auto compute_half = [&](const float (&q)[24], bool skip0) {
#pragma unroll
        for (int j = 0; j < 8; ++j) {
            if (j == 0 && skip0) continue;
            if (dir == 0)
                step_fwd(q[3*j]+EPSF, q[3*j+1]+EPSF, q[3*j+2]+EPSF);
            else
                step_bwd(q[3*j]+EPSF, q[3*j+1]+EPSF, q[3*j+2]+EPSF);
        }
    };

    auto renorm = [&]() {
        float m = fmaxf(fmaxf(a[0], a[1]), fmaxf(a[2], a[3]));
        m = fmaxf(m, atop * t31f);          // lane 31 owns the top state
        bool ne = (m > 0.f);
        float fac = 1.f;
        if (ne) {
            int mb = __float_as_int(m) >> 23;
            if (mb == 0) {                           // denormal max: boost
                const float up = 0x1p126f;
#pragma unroll
                for (int k = 0; k < 4; ++k) a[k] *= up;
                fac *= up;
                E -= 126;
                m *= up;
                mb = __float_as_int(m) >> 23;
            }
            float scale = __int_as_float((254 - mb) << 23);   // exact 2^{-e}
#pragma unroll
            for (int k = 0; k < 4; ++k) a[k] *= scale;
            fac *= scale;
            E += mb - 127;
        }
        atop *= fac;                       // lane-local; only lane31 matters
        unsigned bm = __ballot_sync(FULLMASK, ne);
        if (dir == 0) {          // mass flows low->high lanes
            unsigned below = bm & ((2u << lane) - 1u);
            int src = below ? (31 - __clz(below)) : lane;
            int Ead = __shfl_sync(FULLMASK, E, src);
            if (!ne) E = Ead;
            int Ep = __shfl_up_sync(FULLMASK, E, 1);
            int d = Ep - E;
            d = max(-127, min(120, d));
            f = (bnd || d <= -127) ? 0.f : __int_as_float((d + 127) << 23);
        } else {                 // mass flows high->low lanes
            unsigned up = bm & ~((1u << lane) - 1u);
            int src = up ? (__ffs(up) - 1) : lane;
            int Ead = __shfl_sync(FULLMASK, E, src);
            if (!ne) E = Ead;
            int Ep = __shfl_down_sync(FULLMASK, E, 1);
            int d = Ep - E;
            d = max(-127, min(120, d));
            f = (bnd || d <= -127) ? 0.f : __int_as_float((d + 127) << 23);
        }
    };

    // step->row bases within a chunk: fwd half0 rows 0..7, half1 8..15;
    // bwd half0 rows 15..8, half1 7..0.
    const int h0b = dir ? 15 : 0, h1b = dir ? 7 : 8, stp = dir ? -1 : 1;

    // ---- pipeline: depth-3 prologue + register half-chunk double buffer ----
    issue(0); issue(1); issue(2);
    asm volatile("cp.async.wait_group 2;\n" ::: "memory");
    __syncwarp();

    float qA[24], qB[24];
    load_half(qA, wring, h0b, stp);                  // chunk 0, half 0

#pragma unroll 1
    for (int i = 0; i < NCH; ++i) {
        const float* sb = wring + (i & (STG - 1)) * CHF;
        if (i + 3 < NCH) issue(i + 3);

        load_half(qB, sb, h1b, stp);                 // half 1 of chunk i
        compute_half(qA, (dir == 0 && i == 0));      // half 0 of chunk i
        renorm();

        if (i + 1 < NCH) {
            if (i <= NCH - 4)
                asm volatile("cp.async.wait_group 2;\n" ::: "memory");
            else if (i == NCH - 3)
                asm volatile("cp.async.wait_group 1;\n" ::: "memory");
            else
                asm volatile("cp.async.wait_group 0;\n" ::: "memory");
            __syncwarp();
            const float* sbn = wring + ((i + 1) & (STG - 1)) * CHF;
            load_half(qA, sbn, h0b, stp);            // half 0 of chunk i+1
        }
        compute_half(qB, false);                     // half 1 of chunk i
        renorm();
    }

    // ---- combine: loss = -log( sum_{s=0..128} alpha_255(s)*beta_255(s) ) ----
    if (dir == 1) {
        float* rb = resB + (rowi * 32 + lane) * 5;
#pragma unroll
        for (int k = 0; k < 4; ++k) rb[k] = a[k];
        rb[4] = atop;                              // beta(128), lane31 scale
        resE[rowi * 32 + lane] = E;
    }
    __syncthreads();
    if (dir == 0) {
        const float* rb = resB + (rowi * 32 + lane) * 5;
        double sd = 0.0;
#pragma unroll
        for (int k = 0; k < 4; ++k)
            sd += (double)a[k] * (double)rb[k];
        sd += (double)(t31f * atop) * (double)rb[4];   // s=128 term, lane 31
        int X = E + resE[rowi * 32 + lane];
        bool valid = (sd > 0.0);
        int es = valid ? ilogb(sd) : 0;
        int key = valid ? (X + es) : -1000000000;
        int M = key;
#pragma unroll
        for (int o = 16; o > 0; o >>= 1)
            M = max(M, __shfl_xor_sync(FULLMASK, M, o));
        float term = 0.f;
        if (valid) {
            double mant = scalbn(sd, -es);     // in [1,2)
            int d = key - M;
            if (d >= -126) term = (float)mant * __int_as_float((d + 127) << 23);
        }
#pragma unroll
        for (int o = 16; o > 0; o >>= 1)
            term += __shfl_xor_sync(FULLMASK, term, o);
        if (lane == 0)
            out[b] = (float)(-(log((double)term)
                              + (double)M * 0.6931471805599453));
    }
}

extern "C" void kernel_launch(void* const* d_in, const int* in_sizes, int n_in,
                              void* d_out, int out_size)
{
    int iy = 0, ip = 1;
    if (n_in >= 2 && in_sizes[0] > in_sizes[1]) { iy = 1; ip = 0; }
    const int* y_true = (const int*)d_in[iy];
    const float* y_pred = (const float*)d_in[ip];
    float* out = (float*)d_out;
    int B = in_sizes[iy] / L_DIM;                 // 512
    static bool configured = false;
    if (!configured) {
        cudaFuncSetAttribute(ctc_fb_kernel,
                             cudaFuncAttributeMaxDynamicSharedMemorySize,
                             SMEM_BYTES);
        configured = true;
    }
    int grid = (B + ROWS_PB - 1) / ROWS_PB;       // 128
    ctc_fb_kernel<<<grid, 256, SMEM_BYTES>>>(y_true, y_pred, out, B);
}